// round 4
// baseline (speedup 1.0000x reference)
#include <cuda_runtime.h>
#include <math.h>

#define B      64
#define T      200
#define Q      4096
#define Q2     (2*Q)
#define TM1    (T-1)          // 199
#define NROW   (B*TM1)        // 12736
#define NPROBE 12             // probe rows s = 16, 32, ..., 192

// Scratch (no device allocation allowed in kernel_launch)
__device__ float g_p[NROW];
__device__ float g_a[NROW];
__device__ int   g_flag[NROW];
__device__ int   g_probe[B * NPROBE];
__device__ float g_lossb[B];
__device__ int   g_count;      // zero-initialized; self-resets each replay

// ---------------------------------------------------------------------------
// Record p/a/flag for output row (b, t) given one-hot index j (or -1).
// ---------------------------------------------------------------------------
__device__ __forceinline__ void store_row(const float* __restrict__ pred,
                                          int b, int t, int j)
{
    if (threadIdx.x == 0) {
        float p = 0.0f, a = 0.0f;
        int fl = 0;
        if (j >= 0) {
            const int q = j & (Q - 1);
            a  = (j < Q) ? 1.0f : 0.0f;
            p  = __ldg(pred + ((size_t)b * T + t) * (size_t)Q + q);
            fl = 1;
        }
        const int row = b * TM1 + t;
        g_p[row]    = p;
        g_a[row]    = a;
        g_flag[row] = fl;
    }
}

__device__ __forceinline__ int check4(float4 v, int vi, int f)
{
    if (v.x != 0.0f) f = vi * 4 + 0;
    if (v.y != 0.0f) f = vi * 4 + 1;
    if (v.z != 0.0f) f = vi * 4 + 2;
    if (v.w != 0.0f) f = vi * 4 + 3;
    return f;
}

// ---------------------------------------------------------------------------
// K1: probe rows s = 16k (k=1..12). Full-row read at MLP=8 (no early exit —
// half the probes are all-zero and must read everything anyway). One barrier.
// ---------------------------------------------------------------------------
__global__ __launch_bounds__(256)
void probe_kernel(const float* __restrict__ pred,
                  const float* __restrict__ batch)
{
    const int b = blockIdx.x / NPROBE;
    const int k = blockIdx.x % NPROBE;
    const int s = 16 * (k + 1);
    const int tid = threadIdx.x;

    const float4* __restrict__ base =
        reinterpret_cast<const float4*>(batch + ((size_t)b * T + s) * (size_t)Q2);

    __shared__ int s_idx;
    if (tid == 0) s_idx = -1;
    __syncthreads();

    float4 v[8];
    #pragma unroll
    for (int c = 0; c < 8; ++c) v[c] = base[c * 256 + tid];   // all in flight

    int f = -1;
    #pragma unroll
    for (int c = 0; c < 8; ++c) f = check4(v[c], c * 256 + tid, f);

    if (f >= 0) s_idx = f;            // at most one thread writes
    __syncthreads();

    store_row(pred, b, s - 1, s_idx);
    if (tid == 0) g_probe[b * NPROBE + k] = (s_idx >= 0) ? 1 : 0;
}

// ---------------------------------------------------------------------------
// Two-stage row scan: first half-row (4 loads in flight), test; only if not
// found, second half-row. <=2 barriers, MLP=4.
// ---------------------------------------------------------------------------
__device__ __forceinline__ int scan_row2(const float* __restrict__ batch,
                                         int b, int s)
{
    const float4* __restrict__ base =
        reinterpret_cast<const float4*>(batch + ((size_t)b * T + s) * (size_t)Q2);
    const int tid = threadIdx.x;

    __shared__ int s_idx;
    if (tid == 0) s_idx = -1;
    __syncthreads();

    float4 v0 = base[tid];
    float4 v1 = base[256 + tid];
    float4 v2 = base[512 + tid];
    float4 v3 = base[768 + tid];
    int f = -1;
    f = check4(v0, tid, f);
    f = check4(v1, 256 + tid, f);
    f = check4(v2, 512 + tid, f);
    f = check4(v3, 768 + tid, f);
    if (f >= 0) s_idx = f;

    if (!__syncthreads_or(f >= 0)) {
        v0 = base[1024 + tid];
        v1 = base[1280 + tid];
        v2 = base[1536 + tid];
        v3 = base[1792 + tid];
        f = -1;
        f = check4(v0, 1024 + tid, f);
        f = check4(v1, 1280 + tid, f);
        f = check4(v2, 1536 + tid, f);
        f = check4(v3, 1792 + tid, f);
        if (f >= 0) s_idx = f;
        __syncthreads();
    }
    return s_idx;
}

// ---------------------------------------------------------------------------
// Epilogue, run by the LAST scan block. Warp w handles batches b = w, w+8,...
// All reductions in fixed order (deterministic).
// Output layout: [0]=loss, [1..1+N)=p*maskf, [1+N..1+2N)=a*maskf,
//                [1+2N..1+3N)=mask, N = B*TM1.
// ---------------------------------------------------------------------------
__device__ void run_epilogue(const int* __restrict__ isTestP,
                             const int* __restrict__ tslP,
                             float* __restrict__ d_out)
{
    const int tid  = threadIdx.x;
    const int warp = tid >> 5;
    const int lane = tid & 31;
    const int isTest = *isTestP;
    const int tsl    = *tslP;

    for (int b = warp; b < B; b += 8) {
        // last = max index with flag>0 (warp max-reduce)
        int myLast = -1;
        for (int t = lane; t < TM1; t += 32)
            if (g_flag[b * TM1 + t] > 0) myLast = t;   // increasing t: max kept
        #pragma unroll
        for (int off = 16; off > 0; off >>= 1)
            myLast = max(myLast, __shfl_xor_sync(0xffffffffu, myLast, off));
        const int last = max(myLast, 0);

        int start = 0;
        if (isTest) {
            const int length = last + 1;
            start = (length > tsl) ? (length - tsl) : 0;
        }
        const float cnt = (float)(last - start + 1);

        float sum = 0.0f;
        for (int t = lane; t < TM1; t += 32) {
            const int idx = b * TM1 + t;
            const float p = g_p[idx];
            const float a = g_a[idx];
            const float maskf = (t >= start && t <= last) ? 1.0f : 0.0f;
            const float logp = fmaxf(logf(p), -100.0f);
            const float l1mp = fmaxf(log1pf(-p), -100.0f);
            sum += -(a * logp + (1.0f - a) * l1mp) * maskf;

            d_out[1 + idx]            = p * maskf;
            d_out[1 + NROW + idx]     = a * maskf;
            d_out[1 + 2 * NROW + idx] = maskf;
        }
        #pragma unroll
        for (int off = 16; off > 0; off >>= 1)
            sum += __shfl_xor_sync(0xffffffffu, sum, off);
        if (lane == 0) g_lossb[b] = sum / cnt;
    }
    __syncthreads();

    __shared__ float s2[64];
    if (tid < 64) s2[tid] = g_lossb[tid];
    __syncthreads();
    #pragma unroll
    for (int off = 32; off > 0; off >>= 1) {
        if (tid < off) s2[tid] += s2[tid + off];
        __syncthreads();
    }
    if (tid == 0) {
        d_out[0] = s2[0];
        g_count  = 0;                 // reset for next graph replay
    }
}

// ---------------------------------------------------------------------------
// K2: main scan + fused epilogue on the last block.
// ---------------------------------------------------------------------------
__global__ __launch_bounds__(256)
void scan_kernel(const float* __restrict__ pred,
                 const float* __restrict__ batch,
                 const int*   __restrict__ isTestP,
                 const int*   __restrict__ tslP,
                 float*       __restrict__ d_out)
{
    const int row = blockIdx.x;
    const int b   = row / TM1;
    const int t   = row % TM1;
    const int s   = t + 1;

    const bool probeRow = (s <= 192 && (s & 15) == 0);   // done by probe_kernel

    if (!probeRow) {
        __shared__ int s_ub;
        if (threadIdx.x == 0) {
            int ub = 200;
            #pragma unroll
            for (int k = 0; k < NPROBE; ++k) {
                const int sk = 16 * (k + 1);
                if (!g_probe[b * NPROBE + k] && sk < ub) ub = sk;
            }
            s_ub = ub;
        }
        __syncthreads();

        if (s >= s_ub) {
            store_row(pred, b, t, -1);        // provably all-zero: no reads
        } else {
            const int j = scan_row2(batch, b, s);
            store_row(pred, b, t, j);
        }
    }

    // last-block-runs-epilogue
    __shared__ bool s_last;
    if (threadIdx.x == 0) {
        __threadfence();
        s_last = (atomicAdd(&g_count, 1) == NROW - 1);
    }
    __syncthreads();
    if (s_last) {
        __threadfence();
        run_epilogue(isTestP, tslP, d_out);
    }
}

extern "C" void kernel_launch(void* const* d_in, const int* in_sizes, int n_in,
                              void* d_out, int out_size)
{
    const float* pred  = (const float*)d_in[0];
    const float* batch = (const float*)d_in[1];
    const int*   isT   = (const int*)d_in[2];
    const int*   tsl   = (const int*)d_in[3];
    float*       out   = (float*)d_out;

    probe_kernel<<<B * NPROBE, 256>>>(pred, batch);
    scan_kernel<<<NROW, 256>>>(pred, batch, isT, tsl, out);
}

// round 5
// speedup vs baseline: 2.0098x; 2.0098x over previous
#include <cuda_runtime.h>
#include <math.h>

#define B      64
#define T      200
#define Q      4096
#define Q2     (2*Q)
#define TM1    (T-1)          // 199
#define NROW   (B*TM1)        // 12736
#define NPROBE 12             // probe rows s = 16, 32, ..., 192

// Scratch (no device allocation allowed in kernel_launch)
__device__ float g_p[NROW];
__device__ float g_a[NROW];
__device__ int   g_flag[NROW];
__device__ int   g_probe[B * NPROBE];
__device__ float g_lossb[B];
__device__ int   g_count;      // zero-initialized; self-resets each replay

// ---------------------------------------------------------------------------
// Record p/a/flag for output row (b, t) given one-hot index j (or -1).
// ---------------------------------------------------------------------------
__device__ __forceinline__ void store_row(const float* __restrict__ pred,
                                          int b, int t, int j)
{
    if (threadIdx.x == 0) {
        float p = 0.0f, a = 0.0f;
        int fl = 0;
        if (j >= 0) {
            const int q = j & (Q - 1);
            a  = (j < Q) ? 1.0f : 0.0f;
            p  = __ldg(pred + ((size_t)b * T + t) * (size_t)Q + q);
            fl = 1;
        }
        const int row = b * TM1 + t;
        g_p[row]    = p;
        g_a[row]    = a;
        g_flag[row] = fl;
    }
}

__device__ __forceinline__ int check4(float4 v, int vi, int f)
{
    if (v.x != 0.0f) f = vi * 4 + 0;
    if (v.y != 0.0f) f = vi * 4 + 1;
    if (v.z != 0.0f) f = vi * 4 + 2;
    if (v.w != 0.0f) f = vi * 4 + 3;
    return f;
}

// ---------------------------------------------------------------------------
// K1: probe rows s = 16k (k=1..12). Full-row read with all 8 float4s per
// thread in flight (MLP=8), ONE barrier. No early exit: half the probes are
// all-zero rows and must read everything anyway. Pure-BW kernel, ~24 MB.
// ---------------------------------------------------------------------------
__global__ __launch_bounds__(256)
void probe_kernel(const float* __restrict__ pred,
                  const float* __restrict__ batch)
{
    const int b = blockIdx.x / NPROBE;
    const int k = blockIdx.x % NPROBE;
    const int s = 16 * (k + 1);
    const int tid = threadIdx.x;

    const float4* __restrict__ base =
        reinterpret_cast<const float4*>(batch + ((size_t)b * T + s) * (size_t)Q2);

    __shared__ int s_idx;
    if (tid == 0) s_idx = -1;
    __syncthreads();

    float4 v[8];
    #pragma unroll
    for (int c = 0; c < 8; ++c) v[c] = base[c * 256 + tid];   // all in flight

    int f = -1;
    #pragma unroll
    for (int c = 0; c < 8; ++c) f = check4(v[c], c * 256 + tid, f);

    if (f >= 0) s_idx = f;            // at most one thread writes
    __syncthreads();

    store_row(pred, b, s - 1, s_idx);
    if (tid == 0) g_probe[b * NPROBE + k] = (s_idx >= 0) ? 1 : 0;
}

// ---------------------------------------------------------------------------
// Pipelined early-exit scan (R3, known-good): load for chunk c+1 is issued
// before the barrier deciding exit on chunk c, so the barrier wait covers an
// in-flight load. Over-reads at most one 4 KB chunk.
// ---------------------------------------------------------------------------
__device__ __forceinline__ int scan_row(const float* __restrict__ batch,
                                        int b, int s)
{
    const float4* __restrict__ base =
        reinterpret_cast<const float4*>(batch + ((size_t)b * T + s) * (size_t)Q2);
    const int tid = threadIdx.x;

    __shared__ int s_idx;
    if (tid == 0) s_idx = -1;
    __syncthreads();

    float4 cur = base[tid];
    #pragma unroll 1
    for (int c = 0; c < 8; ++c) {
        float4 nxt = make_float4(0.f, 0.f, 0.f, 0.f);
        if (c < 7) nxt = base[(c + 1) * 256 + tid];

        const int vi = c * 256 + tid;
        int f = check4(cur, vi, -1);
        if (f >= 0) s_idx = f;
        if (__syncthreads_or(f >= 0)) break;
        cur = nxt;
    }
    return s_idx;
}

// ---------------------------------------------------------------------------
// K2: main scan. Probed rows skipped; rows provably past the boundary are
// zero-written with no reads; the rest scan pipelined with early exit.
// NO fences, NO atomics here (R4 lesson: per-block gpu-fence at grid=12k
// flushes L1 chip-wide and serializes).
// ---------------------------------------------------------------------------
__global__ __launch_bounds__(256)
void scan_kernel(const float* __restrict__ pred,
                 const float* __restrict__ batch)
{
    const int row = blockIdx.x;
    const int b   = row / TM1;
    const int t   = row % TM1;
    const int s   = t + 1;

    if (s <= 192 && (s & 15) == 0) return;       // handled by probe_kernel

    __shared__ int s_ub;
    if (threadIdx.x == 0) {
        int ub = 200;
        #pragma unroll
        for (int k = 0; k < NPROBE; ++k) {
            const int sk = 16 * (k + 1);
            if (!g_probe[b * NPROBE + k] && sk < ub) ub = sk;
        }
        s_ub = ub;
    }
    __syncthreads();

    if (s >= s_ub) {                             // provably all-zero row
        store_row(pred, b, t, -1);
        return;
    }
    const int j = scan_row(batch, b, s);
    store_row(pred, b, t, j);
}

// ---------------------------------------------------------------------------
// K3: merged epilogue (grid=64 — fence/atomic cost negligible at this scale).
// Block b: last/start/mask/cnt, BCE, output arrays, per-b loss; the last
// block does the deterministic 64-way sum and resets the counter.
// Output layout: [0]=loss, [1..1+N)=p*maskf, [1+N..1+2N)=a*maskf,
//                [1+2N..1+3N)=mask, N = B*TM1.
// ---------------------------------------------------------------------------
__global__ __launch_bounds__(256)
void epilogue_kernel(const int* __restrict__ isTestP,
                     const int* __restrict__ tslP,
                     float* __restrict__ d_out)
{
    const int b   = blockIdx.x;
    const int tid = threadIdx.x;

    float p = 0.0f, a = 0.0f;
    int myLast = -1;
    if (tid < TM1) {
        const int idx = b * TM1 + tid;
        p = g_p[idx];
        a = g_a[idx];
        if (g_flag[idx] > 0) myLast = tid;
    }

    __shared__ int s_i[256];
    s_i[tid] = myLast;
    __syncthreads();
    #pragma unroll
    for (int off = 128; off > 0; off >>= 1) {
        if (tid < off) s_i[tid] = max(s_i[tid], s_i[tid + off]);
        __syncthreads();
    }
    const int last = max(s_i[0], 0);

    int start = 0;
    if (*isTestP) {
        const int length = last + 1;
        const int tsl = *tslP;
        start = (length > tsl) ? (length - tsl) : 0;
    }

    const bool  m     = (tid < TM1) && (tid >= start) && (tid <= last);
    const float maskf = m ? 1.0f : 0.0f;
    const float cnt   = (float)(last - start + 1);

    float bce = 0.0f;
    if (tid < TM1) {
        const float logp = fmaxf(logf(p), -100.0f);
        const float l1mp = fmaxf(log1pf(-p), -100.0f);
        bce = -(a * logp + (1.0f - a) * l1mp);

        const int idx = b * TM1 + tid;
        d_out[1 + idx]            = p * maskf;
        d_out[1 + NROW + idx]     = a * maskf;
        d_out[1 + 2 * NROW + idx] = maskf;
    }

    __shared__ float s_f[256];
    s_f[tid] = bce * maskf;
    __syncthreads();
    #pragma unroll
    for (int off = 128; off > 0; off >>= 1) {
        if (tid < off) s_f[tid] += s_f[tid + off];
        __syncthreads();
    }

    __shared__ bool s_last;
    if (tid == 0) {
        g_lossb[b] = s_f[0] / cnt;
        __threadfence();
        s_last = (atomicAdd(&g_count, 1) == B - 1);
    }
    __syncthreads();

    if (s_last) {
        __shared__ float s2[64];
        if (tid < B) s2[tid] = g_lossb[tid];
        __syncthreads();
        #pragma unroll
        for (int off = 32; off > 0; off >>= 1) {
            if (tid < off) s2[tid] += s2[tid + off];
            __syncthreads();
        }
        if (tid == 0) {
            d_out[0] = s2[0];
            g_count  = 0;                        // reset for next replay
        }
    }
}

extern "C" void kernel_launch(void* const* d_in, const int* in_sizes, int n_in,
                              void* d_out, int out_size)
{
    const float* pred  = (const float*)d_in[0];
    const float* batch = (const float*)d_in[1];
    const int*   isT   = (const int*)d_in[2];
    const int*   tsl   = (const int*)d_in[3];
    float*       out   = (float*)d_out;

    probe_kernel<<<B * NPROBE, 256>>>(pred, batch);
    scan_kernel<<<NROW, 256>>>(pred, batch);
    epilogue_kernel<<<B, 256>>>(isT, tsl, out);
}